// round 14
// baseline (speedup 1.0000x reference)
#include <cuda_runtime.h>
#include <math.h>
#include <stdint.h>

#define W_ 152
#define H_ 100
#define NPIX 15200
#define NANCH 136800
#define NCAND 8192
#define NHIST 4096
#define PRE_NMS_N 6000
#define POST_NMS_N 300
#define MASK_W 94
#define NTILE 3800          // 50 x 76 winograd tiles
#define NTP 3840            // padded tile count (x128)
#define PLANE (512 * NTP)   // elements per winograd plane

__device__ float g_U[16 * 512 * 512];
__device__ float g_V[16 * PLANE];
__device__ float g_M[16 * PLANE];
__device__ float g_x[512 * NPIX];
__device__ float g_head[54 * NPIX];
__device__ float4 g_boxes[NANCH];
__device__ unsigned long long g_keys[NANCH];
__device__ unsigned long long g_cand[NCAND];
__device__ int g_hist1[NHIST];
__device__ int g_hist2[NHIST];
__device__ int g_b1;
__device__ int g_above1;
__device__ unsigned g_T24;
__device__ int g_count;
__device__ float4 g_top_boxes[PRE_NMS_N];
__device__ unsigned long long g_mask[(size_t)PRE_NMS_N * MASK_W];
__device__ int g_sel[POST_NMS_N];

__constant__ float c_anchors[9][4] = {
    {-84.f,-40.f,99.f,55.f},{-176.f,-88.f,191.f,103.f},{-360.f,-184.f,375.f,199.f},
    {-56.f,-56.f,71.f,71.f},{-120.f,-120.f,135.f,135.f},{-248.f,-248.f,263.f,263.f},
    {-36.f,-80.f,51.f,95.f},{-80.f,-168.f,95.f,183.f},{-168.f,-344.f,183.f,359.f}
};

// ---- weight transform: U = G g G^T  (correlation form, exact halves)
__global__ __launch_bounds__(256) void wino_w_kernel(const float* __restrict__ wgt)
{
    int idx = blockIdx.x * 256 + threadIdx.x;
    if (idx >= 512 * 512) return;
    const float* g = wgt + (size_t)idx * 9;
    float t[4][3];
#pragma unroll
    for (int c = 0; c < 3; c++) {
        float g0 = g[c], g1 = g[3 + c], g2 = g[6 + c];
        t[0][c] = g0;
        t[1][c] = __fmul_rn(0.5f, __fadd_rn(__fadd_rn(g0, g1), g2));
        t[2][c] = __fmul_rn(0.5f, __fadd_rn(__fsub_rn(g0, g1), g2));
        t[3][c] = g2;
    }
#pragma unroll
    for (int i = 0; i < 4; i++) {
        float u0 = t[i][0];
        float u1 = __fmul_rn(0.5f, __fadd_rn(__fadd_rn(t[i][0], t[i][1]), t[i][2]));
        float u2 = __fmul_rn(0.5f, __fadd_rn(__fsub_rn(t[i][0], t[i][1]), t[i][2]));
        float u3 = t[i][2];
        g_U[(i * 4 + 0) * 262144 + idx] = u0;
        g_U[(i * 4 + 1) * 262144 + idx] = u1;
        g_U[(i * 4 + 2) * 262144 + idx] = u2;
        g_U[(i * 4 + 3) * 262144 + idx] = u3;
    }
}

// ---- input transform: V = B^T d B per (ic, tile)
__global__ __launch_bounds__(256) void wino_in_kernel(const float* __restrict__ in)
{
    int idx = blockIdx.x * 256 + threadIdx.x;
    if (idx >= 512 * NTILE) return;
    int ic = idx / NTILE, tile = idx - ic * NTILE;
    int ty = tile / 76, tx = tile - ty * 76;
    int r0 = 2 * ty - 1, c0 = 2 * tx - 1;
    const float* src = in + (size_t)ic * NPIX;
    float d[4][4];
#pragma unroll
    for (int r = 0; r < 4; r++) {
        int rr = r0 + r;
        bool rv = (rr >= 0) && (rr < H_);
#pragma unroll
        for (int c = 0; c < 4; c++) {
            int cc = c0 + c;
            d[r][c] = (rv && cc >= 0 && cc < W_) ? src[rr * W_ + cc] : 0.f;
        }
    }
    float t[4][4];
#pragma unroll
    for (int c = 0; c < 4; c++) {
        t[0][c] = __fsub_rn(d[0][c], d[2][c]);
        t[1][c] = __fadd_rn(d[1][c], d[2][c]);
        t[2][c] = __fsub_rn(d[2][c], d[1][c]);
        t[3][c] = __fsub_rn(d[1][c], d[3][c]);
    }
    size_t base = (size_t)ic * NTP + tile;
#pragma unroll
    for (int i = 0; i < 4; i++) {
        g_V[(size_t)(i * 4 + 0) * PLANE + base] = __fsub_rn(t[i][0], t[i][2]);
        g_V[(size_t)(i * 4 + 1) * PLANE + base] = __fadd_rn(t[i][1], t[i][2]);
        g_V[(size_t)(i * 4 + 2) * PLANE + base] = __fsub_rn(t[i][2], t[i][1]);
        g_V[(size_t)(i * 4 + 3) * PLANE + base] = __fsub_rn(t[i][1], t[i][3]);
    }
}

// ---- 16 batched GEMMs: M_j[512][3840] = U_j[512][512] x V_j[512][3840]
// FFMA2 microkernel with A stored pre-duplicated in smem (no per-kk mov.b64).
// Accumulation chain bit-identical to R13.
__global__ __launch_bounds__(128) void wino_gemm_kernel()
{
    __shared__ float As[2][8][264];   // duplicated pairs: As[..][2i],As[..][2i+1] = A[i]
    __shared__ float Bs[2][8][132];
    const int tid = threadIdx.x;
    const int tx = tid & 7, ty = tid >> 3;
    const int bn = blockIdx.x * 128;
    const int bm = blockIdx.y * 128;
    const int j = blockIdx.z;
    const float* Up = g_U + (size_t)j * 262144 + (size_t)(bm + tid) * 512;
    const float* Vp = g_V + (size_t)j * PLANE;
    float* Mp = g_M + (size_t)j * PLANE;

    unsigned long long acc[8][8];
#pragma unroll
    for (int i = 0; i < 8; i++)
#pragma unroll
        for (int q = 0; q < 8; q++) acc[i][q] = 0ULL;

    float Areg[8], Breg[8];
    auto loadTile = [&](int it, float* ar, float* br) {
        int k0 = it * 8;
        float4 a0 = *reinterpret_cast<const float4*>(Up + k0);
        float4 a1 = *reinterpret_cast<const float4*>(Up + k0 + 4);
        ar[0]=a0.x; ar[1]=a0.y; ar[2]=a0.z; ar[3]=a0.w;
        ar[4]=a1.x; ar[5]=a1.y; ar[6]=a1.z; ar[7]=a1.w;
        const float* vcol = Vp + (size_t)k0 * NTP + bn + tid;
#pragma unroll
        for (int r = 0; r < 8; r++)
            br[r] = __ldg(vcol + (size_t)r * NTP);
    };
    auto storeTile = [&](int buf, const float* ar, const float* br) {
#pragma unroll
        for (int kk = 0; kk < 8; kk++)
            *reinterpret_cast<float2*>(&As[buf][kk][2 * tid]) =
                make_float2(ar[kk], ar[kk]);
#pragma unroll
        for (int kk = 0; kk < 8; kk++) Bs[buf][kk][tid] = br[kk];
    };

    loadTile(0, Areg, Breg);
    storeTile(0, Areg, Breg);
    __syncthreads();

    int cur = 0;
    const int NIT = 64;
    for (int it = 0; it < NIT; it++) {
        bool more = (it + 1 < NIT);
        if (more) loadTile(it + 1, Areg, Breg);

#pragma unroll
        for (int kk = 0; kk < 8; kk++) {
            const ulonglong2* arow =
                reinterpret_cast<const ulonglong2*>(&As[cur][kk][0]);
            const ulonglong2* brow =
                reinterpret_cast<const ulonglong2*>(&Bs[cur][kk][0]);
            unsigned long long b2[8];
#pragma unroll
            for (int q = 0; q < 4; q++) {
                ulonglong2 t = brow[tx + q * 8];
                b2[2 * q] = t.x;
                b2[2 * q + 1] = t.y;
            }
            unsigned long long a2[8];
            {
                ulonglong2 p0 = arow[2 * ty];
                ulonglong2 p1 = arow[2 * ty + 1];
                ulonglong2 p2 = arow[32 + 2 * ty];
                ulonglong2 p3 = arow[32 + 2 * ty + 1];
                a2[0] = p0.x; a2[1] = p0.y; a2[2] = p1.x; a2[3] = p1.y;
                a2[4] = p2.x; a2[5] = p2.y; a2[6] = p3.x; a2[7] = p3.y;
            }
#pragma unroll
            for (int s = 0; s < 8; s++)
#pragma unroll
                for (int q = 0; q < 8; q++)
                    asm("fma.rn.f32x2 %0, %1, %2, %0;"
                        : "+l"(acc[s][q]) : "l"(a2[s]), "l"(b2[q]));
        }

        if (more) {
            storeTile(cur ^ 1, Areg, Breg);
            __syncthreads();
            cur ^= 1;
        }
    }

#pragma unroll
    for (int r = 0; r < 2; r++)
#pragma unroll
        for (int s = 0; s < 4; s++) {
            int m = bm + r * 64 + ty * 4 + s;
#pragma unroll
            for (int q = 0; q < 4; q++)
#pragma unroll
                for (int t = 0; t < 2; t++) {
                    int n = bn + q * 32 + tx * 4 + t * 2;
                    unsigned long long v = acc[r * 4 + s][q * 2 + t];
                    float lo, hi;
                    asm("mov.b64 {%0, %1}, %2;" : "=f"(lo), "=f"(hi) : "l"(v));
                    *reinterpret_cast<float2*>(&Mp[(size_t)m * NTP + n]) =
                        make_float2(lo, hi);
                }
        }
}

// ---- output transform: Y = A^T M A + bias, relu
__global__ __launch_bounds__(256) void wino_out_kernel(const float* __restrict__ bias)
{
    int idx = blockIdx.x * 256 + threadIdx.x;
    if (idx >= 512 * NTILE) return;
    int oc = idx / NTILE, tile = idx - oc * NTILE;
    int ty = tile / 76, tx = tile - ty * 76;
    size_t base = (size_t)oc * NTP + tile;
    float m[16];
#pragma unroll
    for (int j = 0; j < 16; j++)
        m[j] = g_M[(size_t)j * PLANE + base];
    float t0[4], t1[4];
#pragma unroll
    for (int c = 0; c < 4; c++) {
        t0[c] = __fadd_rn(__fadd_rn(m[c], m[4 + c]), m[8 + c]);
        t1[c] = __fsub_rn(__fsub_rn(m[4 + c], m[8 + c]), m[12 + c]);
    }
    float bv = bias[oc];
    float y00 = __fadd_rn(__fadd_rn(t0[0], t0[1]), t0[2]);
    float y01 = __fsub_rn(__fsub_rn(t0[1], t0[2]), t0[3]);
    float y10 = __fadd_rn(__fadd_rn(t1[0], t1[1]), t1[2]);
    float y11 = __fsub_rn(__fsub_rn(t1[1], t1[2]), t1[3]);
    float* dst = g_x + (size_t)oc * NPIX + (2 * ty) * W_ + 2 * tx;
    dst[0]      = fmaxf(__fadd_rn(y00, bv), 0.f);
    dst[1]      = fmaxf(__fadd_rn(y01, bv), 0.f);
    dst[W_]     = fmaxf(__fadd_rn(y10, bv), 0.f);
    dst[W_ + 1] = fmaxf(__fadd_rn(y11, bv), 0.f);
}

// ---- heads: BN=64 (grid 238)
__global__ __launch_bounds__(256) void head_kernel(
    const float* __restrict__ cls_w, const float* __restrict__ cls_b,
    const float* __restrict__ bbox_w, const float* __restrict__ bbox_b)
{
    __shared__ float As[16][68];
    __shared__ float Bs[16][68];
    const int tid = threadIdx.x;
    const int bn = blockIdx.x * 64;
    const int tx = tid & 15, ty = tid >> 4;

    float acc[4][4];
#pragma unroll
    for (int i = 0; i < 4; i++)
#pragma unroll
        for (int j = 0; j < 4; j++) acc[i][j] = 0.f;

    for (int k0 = 0; k0 < 512; k0 += 16) {
        {
            int m = tid >> 2, kq = (tid & 3) << 2;
            float4 v = make_float4(0.f, 0.f, 0.f, 0.f);
            if (m < 18) v = *reinterpret_cast<const float4*>(cls_w + (size_t)m * 512 + k0 + kq);
            else if (m < 54) v = *reinterpret_cast<const float4*>(bbox_w + (size_t)(m - 18) * 512 + k0 + kq);
            As[kq + 0][m] = v.x; As[kq + 1][m] = v.y; As[kq + 2][m] = v.z; As[kq + 3][m] = v.w;
        }
#pragma unroll
        for (int r = 0; r < 4; r++) {
            int e = r * 256 + tid, kk = e >> 6, nn = e & 63, p = bn + nn;
            Bs[kk][nn] = (p < NPIX) ? g_x[(size_t)(k0 + kk) * NPIX + p] : 0.f;
        }
        __syncthreads();
#pragma unroll
        for (int kk = 0; kk < 16; kk++) {
            float a[4], b[4];
            float4 a0 = *reinterpret_cast<float4*>(&As[kk][ty * 4]);
            float4 b0 = *reinterpret_cast<float4*>(&Bs[kk][tx * 4]);
            a[0]=a0.x; a[1]=a0.y; a[2]=a0.z; a[3]=a0.w;
            b[0]=b0.x; b[1]=b0.y; b[2]=b0.z; b[3]=b0.w;
#pragma unroll
            for (int i = 0; i < 4; i++)
#pragma unroll
                for (int j = 0; j < 4; j++)
                    acc[i][j] = __fmaf_rn(a[i], b[j], acc[i][j]);
        }
        __syncthreads();
    }
#pragma unroll
    for (int i = 0; i < 4; i++) {
        int m = ty * 4 + i;
        if (m >= 54) continue;
        float bv = (m < 18) ? cls_b[m] : bbox_b[m - 18];
#pragma unroll
        for (int j = 0; j < 4; j++) {
            int n = bn + tx * 4 + j;
            if (n < NPIX) g_head[(size_t)m * NPIX + n] = __fadd_rn(acc[i][j], bv);
        }
    }
}

__global__ void zero_sel_kernel()
{
    int idx = blockIdx.x * 256 + threadIdx.x;
    if (idx < NCAND) g_cand[idx] = 0ULL;
    if (idx < NHIST) { g_hist1[idx] = 0; g_hist2[idx] = 0; }
    if (idx == 0) g_count = 0;
}

__global__ void decode_kernel(const float* __restrict__ iminfo)
{
    int idx = blockIdx.x * 256 + threadIdx.x;
    if (idx >= NANCH) return;
    int a = idx % 9, p = idx / 9, h = p / W_, w = p - h * W_;

    float s0 = g_head[(size_t)a * NPIX + p];
    float s1 = g_head[(size_t)(9 + a) * NPIX + p];
    float mx = fmaxf(s0, s1);
    float e0 = (float)exp((double)__fsub_rn(s0, mx));
    float e1 = (float)exp((double)__fsub_rn(s1, mx));
    float fg = __fdiv_rn(e1, __fadd_rn(e0, e1));

    float d0 = g_head[(size_t)(18 + a * 4 + 0) * NPIX + p];
    float d1 = g_head[(size_t)(18 + a * 4 + 1) * NPIX + p];
    float d2 = g_head[(size_t)(18 + a * 4 + 2) * NPIX + p];
    float d3 = g_head[(size_t)(18 + a * 4 + 3) * NPIX + p];

    float sx = (float)(w * 16), sy = (float)(h * 16);
    float x1a = c_anchors[a][0] + sx, y1a = c_anchors[a][1] + sy;
    float x2a = c_anchors[a][2] + sx, y2a = c_anchors[a][3] + sy;
    float aw = __fadd_rn(__fsub_rn(x2a, x1a), 1.0f);
    float ah = __fadd_rn(__fsub_rn(y2a, y1a), 1.0f);
    float ax = __fadd_rn(x1a, __fmul_rn(0.5f, aw));
    float ay = __fadd_rn(y1a, __fmul_rn(0.5f, ah));

    float px = __fadd_rn(__fmul_rn(d0, aw), ax);
    float py = __fadd_rn(__fmul_rn(d1, ah), ay);
    float pwv = __fmul_rn((float)exp((double)d2), aw);
    float phv = __fmul_rn((float)exp((double)d3), ah);

    float x1 = __fsub_rn(px, __fmul_rn(0.5f, pwv));
    float y1 = __fsub_rn(py, __fmul_rn(0.5f, phv));
    float x2 = __fadd_rn(px, __fmul_rn(0.5f, pwv));
    float y2 = __fadd_rn(py, __fmul_rn(0.5f, phv));

    float hiX = __fsub_rn(iminfo[1], 1.0f);
    float hiY = __fsub_rn(iminfo[0], 1.0f);
    x1 = fminf(fmaxf(x1, 0.f), hiX);
    y1 = fminf(fmaxf(y1, 0.f), hiY);
    x2 = fminf(fmaxf(x2, 0.f), hiX);
    y2 = fminf(fmaxf(y2, 0.f), hiY);

    float ws = __fadd_rn(__fsub_rn(x2, x1), 1.0f);
    float hs = __fadd_rn(__fsub_rn(y2, y1), 1.0f);
    float msz = __fmul_rn(16.0f, iminfo[2]);
    bool valid = (ws >= msz) && (hs >= msz);
    float score = valid ? fg : -1000000000.0f;

    unsigned u = __float_as_uint(score);
    u = (u & 0x80000000u) ? ~u : (u | 0x80000000u);
    g_keys[idx] = ((unsigned long long)u << 32) | (unsigned)(~(unsigned)idx);
    g_boxes[idx] = make_float4(x1, y1, x2, y2);
    atomicAdd(&g_hist1[u >> 20], 1);
}

__global__ __launch_bounds__(128) void scan1_kernel()
{
    __shared__ int part[128];
    int t = threadIdx.x, s = 0;
#pragma unroll
    for (int q = 0; q < 32; q++) s += g_hist1[t * 32 + q];
    part[t] = s;
    __syncthreads();
    if (t == 0) {
        int cum = 0, seg = 0;
        for (int pp = 127; pp >= 0; pp--) {
            if (cum + part[pp] >= PRE_NMS_N) { seg = pp; break; }
            cum += part[pp];
            if (pp == 0) seg = 0;
        }
        int b = seg * 32 + 31;
        for (; b >= seg * 32; b--) {
            int c = g_hist1[b];
            if (cum + c >= PRE_NMS_N) break;
            cum += c;
        }
        if (b < seg * 32) b = seg * 32;
        g_b1 = b; g_above1 = cum;
    }
}

__global__ void hist2_kernel()
{
    int idx = blockIdx.x * 256 + threadIdx.x;
    if (idx >= NANCH) return;
    unsigned u = (unsigned)(g_keys[idx] >> 32);
    if ((int)(u >> 20) == g_b1) atomicAdd(&g_hist2[(u >> 8) & 0xFFF], 1);
}

__global__ __launch_bounds__(128) void scan2_kernel()
{
    __shared__ int part[128];
    int t = threadIdx.x, s = 0;
#pragma unroll
    for (int q = 0; q < 32; q++) s += g_hist2[t * 32 + q];
    part[t] = s;
    __syncthreads();
    if (t == 0) {
        int cum = g_above1, seg = 0;
        for (int pp = 127; pp >= 0; pp--) {
            if (cum + part[pp] >= PRE_NMS_N) { seg = pp; break; }
            cum += part[pp];
            if (pp == 0) seg = 0;
        }
        int b = seg * 32 + 31;
        for (; b >= seg * 32; b--) {
            int c = g_hist2[b];
            if (cum + c >= PRE_NMS_N) break;
            cum += c;
        }
        if (b < seg * 32) b = seg * 32;
        g_T24 = ((unsigned)g_b1 << 12) | (unsigned)b;
    }
}

__global__ void compact_kernel()
{
    int idx = blockIdx.x * 256 + threadIdx.x;
    if (idx >= NANCH) return;
    unsigned long long key = g_keys[idx];
    unsigned u = (unsigned)(key >> 32);
    if ((u >> 8) >= g_T24) {
        int pos = atomicAdd(&g_count, 1);
        if (pos < NCAND) g_cand[pos] = key;
    }
}

__device__ __forceinline__ bool bt_sw(unsigned long long a, unsigned long long b, bool up)
{
    return up ? (a > b) : (a < b);
}

__global__ __launch_bounds__(1024) void cand_local_kernel()
{
    __shared__ unsigned long long s[4096];
    int base = blockIdx.x * 4096;
    for (int e = threadIdx.x; e < 4096; e += 1024) s[e] = g_cand[base + e];
    __syncthreads();
    for (int k = 2; k <= 4096; k <<= 1)
        for (int j = k >> 1; j > 0; j >>= 1) {
            for (int t = threadIdx.x; t < 2048; t += 1024) {
                int i1 = ((t & ~(j - 1)) << 1) | (t & (j - 1));
                int i2 = i1 + j;
                bool up = (((base + i1) & k) != 0);
                unsigned long long a = s[i1], b = s[i2];
                if (bt_sw(a, b, up)) { s[i1] = b; s[i2] = a; }
            }
            __syncthreads();
        }
    for (int e = threadIdx.x; e < 4096; e += 1024) g_cand[base + e] = s[e];
}

__global__ __launch_bounds__(256) void cand_global_kernel(int k, int j)
{
    int t = blockIdx.x * 256 + threadIdx.x;
    int i1 = ((t & ~(j - 1)) << 1) | (t & (j - 1));
    int i2 = i1 + j;
    bool up = ((i1 & k) != 0);
    unsigned long long a = g_cand[i1], b = g_cand[i2];
    if (bt_sw(a, b, up)) { g_cand[i1] = b; g_cand[i2] = a; }
}

__global__ __launch_bounds__(1024) void cand_fused_kernel(int k)
{
    __shared__ unsigned long long s[4096];
    int base = blockIdx.x * 4096;
    for (int e = threadIdx.x; e < 4096; e += 1024) s[e] = g_cand[base + e];
    __syncthreads();
    for (int j = 2048; j > 0; j >>= 1) {
        for (int t = threadIdx.x; t < 2048; t += 1024) {
            int i1 = ((t & ~(j - 1)) << 1) | (t & (j - 1));
            int i2 = i1 + j;
            bool up = (((base + i1) & k) != 0);
            unsigned long long a = s[i1], b = s[i2];
            if (bt_sw(a, b, up)) { s[i1] = b; s[i2] = a; }
        }
        __syncthreads();
    }
    for (int e = threadIdx.x; e < 4096; e += 1024) g_cand[base + e] = s[e];
}

__global__ void gather_kernel()
{
    int i = blockIdx.x * 256 + threadIdx.x;
    if (i >= PRE_NMS_N) return;
    unsigned idx = ~((unsigned)(g_cand[i] & 0xFFFFFFFFULL));
    g_top_boxes[i] = g_boxes[idx];
}

__global__ __launch_bounds__(64) void nms_mask_kernel()
{
    int rb = blockIdx.y, cb = blockIdx.x;
    if (cb < rb) return;
    __shared__ float4 cbox[64];
    int tid = threadIdx.x;
    int col0 = cb * 64;
    int ccount = min(PRE_NMS_N - col0, 64);
    if (tid < ccount) cbox[tid] = g_top_boxes[col0 + tid];
    __syncthreads();
    int i = rb * 64 + tid;
    if (i >= PRE_NMS_N) return;
    float4 bi = g_top_boxes[i];
    float ai = __fmul_rn(__fadd_rn(__fsub_rn(bi.z, bi.x), 1.0f),
                         __fadd_rn(__fsub_rn(bi.w, bi.y), 1.0f));
    unsigned long long bits = 0ULL;
    for (int c = 0; c < ccount; c++) {
        int j = col0 + c;
        if (j <= i) continue;
        float4 bj = cbox[c];
        float xx1 = fmaxf(bi.x, bj.x), yy1 = fmaxf(bi.y, bj.y);
        float xx2 = fminf(bi.z, bj.z), yy2 = fminf(bi.w, bj.w);
        float iw = fmaxf(0.f, __fadd_rn(__fsub_rn(xx2, xx1), 1.0f));
        float ih = fmaxf(0.f, __fadd_rn(__fsub_rn(yy2, yy1), 1.0f));
        float inter = __fmul_rn(iw, ih);
        float aj = __fmul_rn(__fadd_rn(__fsub_rn(bj.z, bj.x), 1.0f),
                             __fadd_rn(__fsub_rn(bj.w, bj.y), 1.0f));
        float iou = __fdiv_rn(inter, __fsub_rn(__fadd_rn(ai, aj), inter));
        if (iou > 0.7f) bits |= (1ULL << c);
    }
    g_mask[(size_t)i * MASK_W + cb] = bits;
}

__global__ __launch_bounds__(32) void nms_reduce_kernel()
{
    __shared__ int keptlist[POST_NMS_N];
    const unsigned FULL = 0xffffffffu;
    int lane = threadIdx.x;
    unsigned long long remv0 = 0, remv1 = 0, remv2 = 0;
    unsigned long long kb0 = 0, kb1 = 0, kb2 = 0;
    int nkept = 0;

    for (int w = 0; w < MASK_W && nkept < POST_NMS_N; w++) {
        int owner = (w < 32) ? w : ((w < 64) ? w - 32 : w - 64);
        unsigned long long supp;
        if (w < 32)      supp = __shfl_sync(FULL, remv0, owner);
        else if (w < 64) supp = __shfl_sync(FULL, remv1, owner);
        else             supp = __shfl_sync(FULL, remv2, owner);
        unsigned long long live = ~supp;
        if (w == MASK_W - 1) live &= (1ULL << 48) - 1ULL;

        while (live && nkept < POST_NMS_N) {
            int b = __ffsll((long long)live) - 1;
            int i = (w << 6) + b;
            if (lane == 0) keptlist[nkept] = i;
            nkept++;
            if (lane == owner) {
                if (w < 32)      kb0 |= 1ULL << b;
                else if (w < 64) kb1 |= 1ULL << b;
                else             kb2 |= 1ULL << b;
            }
            const unsigned long long* row = g_mask + (size_t)i * MASK_W;
            remv0 |= row[lane];
            remv1 |= row[lane + 32];
            if (lane + 64 < MASK_W) remv2 |= row[lane + 64];
            unsigned long long supp2;
            if (w < 32)      supp2 = __shfl_sync(FULL, remv0, owner);
            else if (w < 64) supp2 = __shfl_sync(FULL, remv1, owner);
            else             supp2 = __shfl_sync(FULL, remv2, owner);
            live &= ~supp2;
            live &= ~(1ULL << b);
        }
    }

    for (int w = 0; w < MASK_W && nkept < POST_NMS_N; w++) {
        int owner = (w < 32) ? w : ((w < 64) ? w - 32 : w - 64);
        unsigned long long kw;
        if (w < 32)      kw = __shfl_sync(FULL, kb0, owner);
        else if (w < 64) kw = __shfl_sync(FULL, kb1, owner);
        else             kw = __shfl_sync(FULL, kb2, owner);
        unsigned long long live = ~kw;
        if (w == MASK_W - 1) live &= (1ULL << 48) - 1ULL;
        while (live && nkept < POST_NMS_N) {
            int b = __ffsll((long long)live) - 1;
            if (lane == 0) keptlist[nkept] = (w << 6) + b;
            nkept++;
            live &= live - 1;
        }
    }
    __syncwarp();
    for (int t = lane; t < POST_NMS_N; t += 32) g_sel[t] = keptlist[t];
}

__global__ void rois_kernel(float* __restrict__ out)
{
    int t = blockIdx.x * 64 + threadIdx.x;
    if (t >= POST_NMS_N) return;
    float4 b = g_top_boxes[g_sel[t]];
    out[t * 5 + 0] = 0.f;
    out[t * 5 + 1] = b.x;
    out[t * 5 + 2] = b.y;
    out[t * 5 + 3] = b.z;
    out[t * 5 + 4] = b.w;
}

extern "C" void kernel_launch(void* const* d_in, const int* in_sizes, int n_in,
                              void* d_out, int out_size)
{
    const float* feature_map = (const float*)d_in[0];
    const float* im_info     = (const float*)d_in[1];
    const float* conv_w      = (const float*)d_in[2];
    const float* conv_b      = (const float*)d_in[3];
    const float* cls_w       = (const float*)d_in[4];
    const float* cls_b       = (const float*)d_in[5];
    const float* bbox_w      = (const float*)d_in[6];
    const float* bbox_b      = (const float*)d_in[7];
    float* out = (float*)d_out;

    wino_w_kernel<<<(512 * 512 + 255) / 256, 256>>>(conv_w);
    wino_in_kernel<<<(512 * NTILE + 255) / 256, 256>>>(feature_map);
    wino_gemm_kernel<<<dim3(NTP / 128, 4, 16), 128>>>();
    wino_out_kernel<<<(512 * NTILE + 255) / 256, 256>>>(conv_b);

    zero_sel_kernel<<<(NCAND + 255) / 256, 256>>>();
    head_kernel<<<(NPIX + 63) / 64, 256>>>(cls_w, cls_b, bbox_w, bbox_b);
    decode_kernel<<<(NANCH + 255) / 256, 256>>>(im_info);

    scan1_kernel<<<1, 128>>>();
    hist2_kernel<<<(NANCH + 255) / 256, 256>>>();
    scan2_kernel<<<1, 128>>>();
    compact_kernel<<<(NANCH + 255) / 256, 256>>>();

    cand_local_kernel<<<NCAND / 4096, 1024>>>();
    cand_global_kernel<<<NCAND / 512, 256>>>(NCAND, NCAND / 2);
    cand_fused_kernel<<<NCAND / 4096, 1024>>>(NCAND);

    gather_kernel<<<(PRE_NMS_N + 255) / 256, 256>>>();
    dim3 mgrid(MASK_W, MASK_W);
    nms_mask_kernel<<<mgrid, 64>>>();
    nms_reduce_kernel<<<1, 32>>>();
    rois_kernel<<<(POST_NMS_N + 63) / 64, 64>>>(out);
}

// round 15
// speedup vs baseline: 1.1163x; 1.1163x over previous
#include <cuda_runtime.h>
#include <math.h>
#include <stdint.h>

#define W_ 152
#define H_ 100
#define NPIX 15200
#define NANCH 136800
#define NCAND 8192
#define NHIST 4096
#define PRE_NMS_N 6000
#define POST_NMS_N 300
#define MASK_W 94
#define NTILE 3800          // 50 x 76 winograd tiles
#define NTP 3840            // padded tile count (x128)
#define PLANE (512 * NTP)   // elements per winograd plane

__device__ float g_U[16 * 512 * 512];
__device__ float g_V[16 * PLANE];
__device__ float g_M[16 * PLANE];
__device__ float g_x[512 * NPIX];
__device__ float g_head[54 * NPIX];
__device__ float4 g_boxes[NANCH];
__device__ unsigned long long g_keys[NANCH];
__device__ unsigned long long g_cand[NCAND];
__device__ int g_hist1[NHIST];
__device__ int g_hist2[NHIST];
__device__ int g_b1;
__device__ int g_above1;
__device__ unsigned g_T24;
__device__ int g_count;
__device__ float4 g_top_boxes[PRE_NMS_N];
__device__ unsigned long long g_mask[(size_t)PRE_NMS_N * MASK_W];
__device__ int g_sel[POST_NMS_N];

__constant__ float c_anchors[9][4] = {
    {-84.f,-40.f,99.f,55.f},{-176.f,-88.f,191.f,103.f},{-360.f,-184.f,375.f,199.f},
    {-56.f,-56.f,71.f,71.f},{-120.f,-120.f,135.f,135.f},{-248.f,-248.f,263.f,263.f},
    {-36.f,-80.f,51.f,95.f},{-80.f,-168.f,95.f,183.f},{-168.f,-344.f,183.f,359.f}
};

// ---- weight transform: U = G g G^T  (correlation form, exact halves)
__global__ __launch_bounds__(256) void wino_w_kernel(const float* __restrict__ wgt)
{
    int idx = blockIdx.x * 256 + threadIdx.x;
    if (idx >= 512 * 512) return;
    const float* g = wgt + (size_t)idx * 9;
    float t[4][3];
#pragma unroll
    for (int c = 0; c < 3; c++) {
        float g0 = g[c], g1 = g[3 + c], g2 = g[6 + c];
        t[0][c] = g0;
        t[1][c] = __fmul_rn(0.5f, __fadd_rn(__fadd_rn(g0, g1), g2));
        t[2][c] = __fmul_rn(0.5f, __fadd_rn(__fsub_rn(g0, g1), g2));
        t[3][c] = g2;
    }
#pragma unroll
    for (int i = 0; i < 4; i++) {
        float u0 = t[i][0];
        float u1 = __fmul_rn(0.5f, __fadd_rn(__fadd_rn(t[i][0], t[i][1]), t[i][2]));
        float u2 = __fmul_rn(0.5f, __fadd_rn(__fsub_rn(t[i][0], t[i][1]), t[i][2]));
        float u3 = t[i][2];
        g_U[(i * 4 + 0) * 262144 + idx] = u0;
        g_U[(i * 4 + 1) * 262144 + idx] = u1;
        g_U[(i * 4 + 2) * 262144 + idx] = u2;
        g_U[(i * 4 + 3) * 262144 + idx] = u3;
    }
}

// ---- input transform: V = B^T d B per (ic, tile)
__global__ __launch_bounds__(256) void wino_in_kernel(const float* __restrict__ in)
{
    int idx = blockIdx.x * 256 + threadIdx.x;
    if (idx >= 512 * NTILE) return;
    int ic = idx / NTILE, tile = idx - ic * NTILE;
    int ty = tile / 76, tx = tile - ty * 76;
    int r0 = 2 * ty - 1, c0 = 2 * tx - 1;
    const float* src = in + (size_t)ic * NPIX;
    float d[4][4];
#pragma unroll
    for (int r = 0; r < 4; r++) {
        int rr = r0 + r;
        bool rv = (rr >= 0) && (rr < H_);
#pragma unroll
        for (int c = 0; c < 4; c++) {
            int cc = c0 + c;
            d[r][c] = (rv && cc >= 0 && cc < W_) ? src[rr * W_ + cc] : 0.f;
        }
    }
    float t[4][4];
#pragma unroll
    for (int c = 0; c < 4; c++) {
        t[0][c] = __fsub_rn(d[0][c], d[2][c]);
        t[1][c] = __fadd_rn(d[1][c], d[2][c]);
        t[2][c] = __fsub_rn(d[2][c], d[1][c]);
        t[3][c] = __fsub_rn(d[1][c], d[3][c]);
    }
    size_t base = (size_t)ic * NTP + tile;
#pragma unroll
    for (int i = 0; i < 4; i++) {
        g_V[(size_t)(i * 4 + 0) * PLANE + base] = __fsub_rn(t[i][0], t[i][2]);
        g_V[(size_t)(i * 4 + 1) * PLANE + base] = __fadd_rn(t[i][1], t[i][2]);
        g_V[(size_t)(i * 4 + 2) * PLANE + base] = __fsub_rn(t[i][2], t[i][1]);
        g_V[(size_t)(i * 4 + 3) * PLANE + base] = __fsub_rn(t[i][1], t[i][3]);
    }
}

// ---- 16 batched GEMMs: M_j[512][3840] = U_j[512][512] x V_j[512][3840]
// R13 FFMA2 microkernel (inner loop byte-identical); B gmem->smem path vectorized
// to 2x LDG.128 + 2x STS.128 per thread per iter (pure data movement, no numeric change).
__global__ __launch_bounds__(128) void wino_gemm_kernel()
{
    __shared__ float As[2][8][132];
    __shared__ float Bs[2][8][132];
    const int tid = threadIdx.x;
    const int tx = tid & 7, ty = tid >> 3;
    const int bn = blockIdx.x * 128;
    const int bm = blockIdx.y * 128;
    const int j = blockIdx.z;
    const float* Up = g_U + (size_t)j * 262144 + (size_t)(bm + tid) * 512;
    const float* Vp = g_V + (size_t)j * PLANE;
    float* Mp = g_M + (size_t)j * PLANE;

    // B loader mapping: row rB and rB+4, 16B chunk cB
    const int rB = tid >> 5;            // 0..3
    const int cB = (tid & 31) * 4;      // 0..124

    unsigned long long acc[8][8];
#pragma unroll
    for (int i = 0; i < 8; i++)
#pragma unroll
        for (int q = 0; q < 8; q++) acc[i][q] = 0ULL;

    float Areg[8];
    float4 Breg0, Breg1;
    auto loadTile = [&](int it) {
        int k0 = it * 8;
        float4 a0 = *reinterpret_cast<const float4*>(Up + k0);
        float4 a1 = *reinterpret_cast<const float4*>(Up + k0 + 4);
        Areg[0]=a0.x; Areg[1]=a0.y; Areg[2]=a0.z; Areg[3]=a0.w;
        Areg[4]=a1.x; Areg[5]=a1.y; Areg[6]=a1.z; Areg[7]=a1.w;
        Breg0 = *reinterpret_cast<const float4*>(
            Vp + (size_t)(k0 + rB) * NTP + bn + cB);
        Breg1 = *reinterpret_cast<const float4*>(
            Vp + (size_t)(k0 + rB + 4) * NTP + bn + cB);
    };
    auto storeTile = [&](int buf) {
#pragma unroll
        for (int kk = 0; kk < 8; kk++) As[buf][kk][tid] = Areg[kk];
        *reinterpret_cast<float4*>(&Bs[buf][rB][cB]) = Breg0;
        *reinterpret_cast<float4*>(&Bs[buf][rB + 4][cB]) = Breg1;
    };

    loadTile(0);
    storeTile(0);
    __syncthreads();

    int cur = 0;
    const int NIT = 64;
    for (int it = 0; it < NIT; it++) {
        bool more = (it + 1 < NIT);
        if (more) loadTile(it + 1);

#pragma unroll
        for (int kk = 0; kk < 8; kk++) {
            const float4* arow = reinterpret_cast<const float4*>(&As[cur][kk][0]);
            const ulonglong2* brow = reinterpret_cast<const ulonglong2*>(&Bs[cur][kk][0]);
            unsigned long long b2[8];
#pragma unroll
            for (int q = 0; q < 4; q++) {
                ulonglong2 t = brow[tx + q * 8];
                b2[2 * q] = t.x;
                b2[2 * q + 1] = t.y;
            }
            float4 a0 = arow[ty];
            float4 a1 = arow[ty + 16];
            float av[8];
            av[0]=a0.x; av[1]=a0.y; av[2]=a0.z; av[3]=a0.w;
            av[4]=a1.x; av[5]=a1.y; av[6]=a1.z; av[7]=a1.w;
            unsigned long long a2[8];
#pragma unroll
            for (int s = 0; s < 8; s++)
                asm("mov.b64 %0, {%1, %1};" : "=l"(a2[s]) : "f"(av[s]));
#pragma unroll
            for (int s = 0; s < 8; s++)
#pragma unroll
                for (int q = 0; q < 8; q++)
                    asm("fma.rn.f32x2 %0, %1, %2, %0;"
                        : "+l"(acc[s][q]) : "l"(a2[s]), "l"(b2[q]));
        }

        if (more) {
            storeTile(cur ^ 1);
            __syncthreads();
            cur ^= 1;
        }
    }

#pragma unroll
    for (int r = 0; r < 2; r++)
#pragma unroll
        for (int s = 0; s < 4; s++) {
            int m = bm + r * 64 + ty * 4 + s;
#pragma unroll
            for (int q = 0; q < 4; q++)
#pragma unroll
                for (int t = 0; t < 2; t++) {
                    int n = bn + q * 32 + tx * 4 + t * 2;
                    unsigned long long v = acc[r * 4 + s][q * 2 + t];
                    float lo, hi;
                    asm("mov.b64 {%0, %1}, %2;" : "=f"(lo), "=f"(hi) : "l"(v));
                    *reinterpret_cast<float2*>(&Mp[(size_t)m * NTP + n]) =
                        make_float2(lo, hi);
                }
        }
}

// ---- output transform: Y = A^T M A + bias, relu
__global__ __launch_bounds__(256) void wino_out_kernel(const float* __restrict__ bias)
{
    int idx = blockIdx.x * 256 + threadIdx.x;
    if (idx >= 512 * NTILE) return;
    int oc = idx / NTILE, tile = idx - oc * NTILE;
    int ty = tile / 76, tx = tile - ty * 76;
    size_t base = (size_t)oc * NTP + tile;
    float m[16];
#pragma unroll
    for (int j = 0; j < 16; j++)
        m[j] = g_M[(size_t)j * PLANE + base];
    float t0[4], t1[4];
#pragma unroll
    for (int c = 0; c < 4; c++) {
        t0[c] = __fadd_rn(__fadd_rn(m[c], m[4 + c]), m[8 + c]);
        t1[c] = __fsub_rn(__fsub_rn(m[4 + c], m[8 + c]), m[12 + c]);
    }
    float bv = bias[oc];
    float y00 = __fadd_rn(__fadd_rn(t0[0], t0[1]), t0[2]);
    float y01 = __fsub_rn(__fsub_rn(t0[1], t0[2]), t0[3]);
    float y10 = __fadd_rn(__fadd_rn(t1[0], t1[1]), t1[2]);
    float y11 = __fsub_rn(__fsub_rn(t1[1], t1[2]), t1[3]);
    float* dst = g_x + (size_t)oc * NPIX + (2 * ty) * W_ + 2 * tx;
    dst[0]      = fmaxf(__fadd_rn(y00, bv), 0.f);
    dst[1]      = fmaxf(__fadd_rn(y01, bv), 0.f);
    dst[W_]     = fmaxf(__fadd_rn(y10, bv), 0.f);
    dst[W_ + 1] = fmaxf(__fadd_rn(y11, bv), 0.f);
}

// ---- heads: BN=64 (grid 238)
__global__ __launch_bounds__(256) void head_kernel(
    const float* __restrict__ cls_w, const float* __restrict__ cls_b,
    const float* __restrict__ bbox_w, const float* __restrict__ bbox_b)
{
    __shared__ float As[16][68];
    __shared__ float Bs[16][68];
    const int tid = threadIdx.x;
    const int bn = blockIdx.x * 64;
    const int tx = tid & 15, ty = tid >> 4;

    float acc[4][4];
#pragma unroll
    for (int i = 0; i < 4; i++)
#pragma unroll
        for (int j = 0; j < 4; j++) acc[i][j] = 0.f;

    for (int k0 = 0; k0 < 512; k0 += 16) {
        {
            int m = tid >> 2, kq = (tid & 3) << 2;
            float4 v = make_float4(0.f, 0.f, 0.f, 0.f);
            if (m < 18) v = *reinterpret_cast<const float4*>(cls_w + (size_t)m * 512 + k0 + kq);
            else if (m < 54) v = *reinterpret_cast<const float4*>(bbox_w + (size_t)(m - 18) * 512 + k0 + kq);
            As[kq + 0][m] = v.x; As[kq + 1][m] = v.y; As[kq + 2][m] = v.z; As[kq + 3][m] = v.w;
        }
#pragma unroll
        for (int r = 0; r < 4; r++) {
            int e = r * 256 + tid, kk = e >> 6, nn = e & 63, p = bn + nn;
            Bs[kk][nn] = (p < NPIX) ? g_x[(size_t)(k0 + kk) * NPIX + p] : 0.f;
        }
        __syncthreads();
#pragma unroll
        for (int kk = 0; kk < 16; kk++) {
            float a[4], b[4];
            float4 a0 = *reinterpret_cast<float4*>(&As[kk][ty * 4]);
            float4 b0 = *reinterpret_cast<float4*>(&Bs[kk][tx * 4]);
            a[0]=a0.x; a[1]=a0.y; a[2]=a0.z; a[3]=a0.w;
            b[0]=b0.x; b[1]=b0.y; b[2]=b0.z; b[3]=b0.w;
#pragma unroll
            for (int i = 0; i < 4; i++)
#pragma unroll
                for (int j = 0; j < 4; j++)
                    acc[i][j] = __fmaf_rn(a[i], b[j], acc[i][j]);
        }
        __syncthreads();
    }
#pragma unroll
    for (int i = 0; i < 4; i++) {
        int m = ty * 4 + i;
        if (m >= 54) continue;
        float bv = (m < 18) ? cls_b[m] : bbox_b[m - 18];
#pragma unroll
        for (int j = 0; j < 4; j++) {
            int n = bn + tx * 4 + j;
            if (n < NPIX) g_head[(size_t)m * NPIX + n] = __fadd_rn(acc[i][j], bv);
        }
    }
}

__global__ void zero_sel_kernel()
{
    int idx = blockIdx.x * 256 + threadIdx.x;
    if (idx < NCAND) g_cand[idx] = 0ULL;
    if (idx < NHIST) { g_hist1[idx] = 0; g_hist2[idx] = 0; }
    if (idx == 0) g_count = 0;
}

__global__ void decode_kernel(const float* __restrict__ iminfo)
{
    int idx = blockIdx.x * 256 + threadIdx.x;
    if (idx >= NANCH) return;
    int a = idx % 9, p = idx / 9, h = p / W_, w = p - h * W_;

    float s0 = g_head[(size_t)a * NPIX + p];
    float s1 = g_head[(size_t)(9 + a) * NPIX + p];
    float mx = fmaxf(s0, s1);
    float e0 = (float)exp((double)__fsub_rn(s0, mx));
    float e1 = (float)exp((double)__fsub_rn(s1, mx));
    float fg = __fdiv_rn(e1, __fadd_rn(e0, e1));

    float d0 = g_head[(size_t)(18 + a * 4 + 0) * NPIX + p];
    float d1 = g_head[(size_t)(18 + a * 4 + 1) * NPIX + p];
    float d2 = g_head[(size_t)(18 + a * 4 + 2) * NPIX + p];
    float d3 = g_head[(size_t)(18 + a * 4 + 3) * NPIX + p];

    float sx = (float)(w * 16), sy = (float)(h * 16);
    float x1a = c_anchors[a][0] + sx, y1a = c_anchors[a][1] + sy;
    float x2a = c_anchors[a][2] + sx, y2a = c_anchors[a][3] + sy;
    float aw = __fadd_rn(__fsub_rn(x2a, x1a), 1.0f);
    float ah = __fadd_rn(__fsub_rn(y2a, y1a), 1.0f);
    float ax = __fadd_rn(x1a, __fmul_rn(0.5f, aw));
    float ay = __fadd_rn(y1a, __fmul_rn(0.5f, ah));

    float px = __fadd_rn(__fmul_rn(d0, aw), ax);
    float py = __fadd_rn(__fmul_rn(d1, ah), ay);
    float pwv = __fmul_rn((float)exp((double)d2), aw);
    float phv = __fmul_rn((float)exp((double)d3), ah);

    float x1 = __fsub_rn(px, __fmul_rn(0.5f, pwv));
    float y1 = __fsub_rn(py, __fmul_rn(0.5f, phv));
    float x2 = __fadd_rn(px, __fmul_rn(0.5f, pwv));
    float y2 = __fadd_rn(py, __fmul_rn(0.5f, phv));

    float hiX = __fsub_rn(iminfo[1], 1.0f);
    float hiY = __fsub_rn(iminfo[0], 1.0f);
    x1 = fminf(fmaxf(x1, 0.f), hiX);
    y1 = fminf(fmaxf(y1, 0.f), hiY);
    x2 = fminf(fmaxf(x2, 0.f), hiX);
    y2 = fminf(fmaxf(y2, 0.f), hiY);

    float ws = __fadd_rn(__fsub_rn(x2, x1), 1.0f);
    float hs = __fadd_rn(__fsub_rn(y2, y1), 1.0f);
    float msz = __fmul_rn(16.0f, iminfo[2]);
    bool valid = (ws >= msz) && (hs >= msz);
    float score = valid ? fg : -1000000000.0f;

    unsigned u = __float_as_uint(score);
    u = (u & 0x80000000u) ? ~u : (u | 0x80000000u);
    g_keys[idx] = ((unsigned long long)u << 32) | (unsigned)(~(unsigned)idx);
    g_boxes[idx] = make_float4(x1, y1, x2, y2);
    atomicAdd(&g_hist1[u >> 20], 1);
}

__global__ __launch_bounds__(128) void scan1_kernel()
{
    __shared__ int part[128];
    int t = threadIdx.x, s = 0;
#pragma unroll
    for (int q = 0; q < 32; q++) s += g_hist1[t * 32 + q];
    part[t] = s;
    __syncthreads();
    if (t == 0) {
        int cum = 0, seg = 0;
        for (int pp = 127; pp >= 0; pp--) {
            if (cum + part[pp] >= PRE_NMS_N) { seg = pp; break; }
            cum += part[pp];
            if (pp == 0) seg = 0;
        }
        int b = seg * 32 + 31;
        for (; b >= seg * 32; b--) {
            int c = g_hist1[b];
            if (cum + c >= PRE_NMS_N) break;
            cum += c;
        }
        if (b < seg * 32) b = seg * 32;
        g_b1 = b; g_above1 = cum;
    }
}

__global__ void hist2_kernel()
{
    int idx = blockIdx.x * 256 + threadIdx.x;
    if (idx >= NANCH) return;
    unsigned u = (unsigned)(g_keys[idx] >> 32);
    if ((int)(u >> 20) == g_b1) atomicAdd(&g_hist2[(u >> 8) & 0xFFF], 1);
}

__global__ __launch_bounds__(128) void scan2_kernel()
{
    __shared__ int part[128];
    int t = threadIdx.x, s = 0;
#pragma unroll
    for (int q = 0; q < 32; q++) s += g_hist2[t * 32 + q];
    part[t] = s;
    __syncthreads();
    if (t == 0) {
        int cum = g_above1, seg = 0;
        for (int pp = 127; pp >= 0; pp--) {
            if (cum + part[pp] >= PRE_NMS_N) { seg = pp; break; }
            cum += part[pp];
            if (pp == 0) seg = 0;
        }
        int b = seg * 32 + 31;
        for (; b >= seg * 32; b--) {
            int c = g_hist2[b];
            if (cum + c >= PRE_NMS_N) break;
            cum += c;
        }
        if (b < seg * 32) b = seg * 32;
        g_T24 = ((unsigned)g_b1 << 12) | (unsigned)b;
    }
}

__global__ void compact_kernel()
{
    int idx = blockIdx.x * 256 + threadIdx.x;
    if (idx >= NANCH) return;
    unsigned long long key = g_keys[idx];
    unsigned u = (unsigned)(key >> 32);
    if ((u >> 8) >= g_T24) {
        int pos = atomicAdd(&g_count, 1);
        if (pos < NCAND) g_cand[pos] = key;
    }
}

__device__ __forceinline__ bool bt_sw(unsigned long long a, unsigned long long b, bool up)
{
    return up ? (a > b) : (a < b);
}

__global__ __launch_bounds__(1024) void cand_local_kernel()
{
    __shared__ unsigned long long s[4096];
    int base = blockIdx.x * 4096;
    for (int e = threadIdx.x; e < 4096; e += 1024) s[e] = g_cand[base + e];
    __syncthreads();
    for (int k = 2; k <= 4096; k <<= 1)
        for (int j = k >> 1; j > 0; j >>= 1) {
            for (int t = threadIdx.x; t < 2048; t += 1024) {
                int i1 = ((t & ~(j - 1)) << 1) | (t & (j - 1));
                int i2 = i1 + j;
                bool up = (((base + i1) & k) != 0);
                unsigned long long a = s[i1], b = s[i2];
                if (bt_sw(a, b, up)) { s[i1] = b; s[i2] = a; }
            }
            __syncthreads();
        }
    for (int e = threadIdx.x; e < 4096; e += 1024) g_cand[base + e] = s[e];
}

__global__ __launch_bounds__(256) void cand_global_kernel(int k, int j)
{
    int t = blockIdx.x * 256 + threadIdx.x;
    int i1 = ((t & ~(j - 1)) << 1) | (t & (j - 1));
    int i2 = i1 + j;
    bool up = ((i1 & k) != 0);
    unsigned long long a = g_cand[i1], b = g_cand[i2];
    if (bt_sw(a, b, up)) { g_cand[i1] = b; g_cand[i2] = a; }
}

__global__ __launch_bounds__(1024) void cand_fused_kernel(int k)
{
    __shared__ unsigned long long s[4096];
    int base = blockIdx.x * 4096;
    for (int e = threadIdx.x; e < 4096; e += 1024) s[e] = g_cand[base + e];
    __syncthreads();
    for (int j = 2048; j > 0; j >>= 1) {
        for (int t = threadIdx.x; t < 2048; t += 1024) {
            int i1 = ((t & ~(j - 1)) << 1) | (t & (j - 1));
            int i2 = i1 + j;
            bool up = (((base + i1) & k) != 0);
            unsigned long long a = s[i1], b = s[i2];
            if (bt_sw(a, b, up)) { s[i1] = b; s[i2] = a; }
        }
        __syncthreads();
    }
    for (int e = threadIdx.x; e < 4096; e += 1024) g_cand[base + e] = s[e];
}

__global__ void gather_kernel()
{
    int i = blockIdx.x * 256 + threadIdx.x;
    if (i >= PRE_NMS_N) return;
    unsigned idx = ~((unsigned)(g_cand[i] & 0xFFFFFFFFULL));
    g_top_boxes[i] = g_boxes[idx];
}

__global__ __launch_bounds__(64) void nms_mask_kernel()
{
    int rb = blockIdx.y, cb = blockIdx.x;
    if (cb < rb) return;
    __shared__ float4 cbox[64];
    int tid = threadIdx.x;
    int col0 = cb * 64;
    int ccount = min(PRE_NMS_N - col0, 64);
    if (tid < ccount) cbox[tid] = g_top_boxes[col0 + tid];
    __syncthreads();
    int i = rb * 64 + tid;
    if (i >= PRE_NMS_N) return;
    float4 bi = g_top_boxes[i];
    float ai = __fmul_rn(__fadd_rn(__fsub_rn(bi.z, bi.x), 1.0f),
                         __fadd_rn(__fsub_rn(bi.w, bi.y), 1.0f));
    unsigned long long bits = 0ULL;
    for (int c = 0; c < ccount; c++) {
        int j = col0 + c;
        if (j <= i) continue;
        float4 bj = cbox[c];
        float xx1 = fmaxf(bi.x, bj.x), yy1 = fmaxf(bi.y, bj.y);
        float xx2 = fminf(bi.z, bj.z), yy2 = fminf(bi.w, bj.w);
        float iw = fmaxf(0.f, __fadd_rn(__fsub_rn(xx2, xx1), 1.0f));
        float ih = fmaxf(0.f, __fadd_rn(__fsub_rn(yy2, yy1), 1.0f));
        float inter = __fmul_rn(iw, ih);
        float aj = __fmul_rn(__fadd_rn(__fsub_rn(bj.z, bj.x), 1.0f),
                             __fadd_rn(__fsub_rn(bj.w, bj.y), 1.0f));
        float iou = __fdiv_rn(inter, __fsub_rn(__fadd_rn(ai, aj), inter));
        if (iou > 0.7f) bits |= (1ULL << c);
    }
    g_mask[(size_t)i * MASK_W + cb] = bits;
}

__global__ __launch_bounds__(32) void nms_reduce_kernel()
{
    __shared__ int keptlist[POST_NMS_N];
    const unsigned FULL = 0xffffffffu;
    int lane = threadIdx.x;
    unsigned long long remv0 = 0, remv1 = 0, remv2 = 0;
    unsigned long long kb0 = 0, kb1 = 0, kb2 = 0;
    int nkept = 0;

    for (int w = 0; w < MASK_W && nkept < POST_NMS_N; w++) {
        int owner = (w < 32) ? w : ((w < 64) ? w - 32 : w - 64);
        unsigned long long supp;
        if (w < 32)      supp = __shfl_sync(FULL, remv0, owner);
        else if (w < 64) supp = __shfl_sync(FULL, remv1, owner);
        else             supp = __shfl_sync(FULL, remv2, owner);
        unsigned long long live = ~supp;
        if (w == MASK_W - 1) live &= (1ULL << 48) - 1ULL;

        while (live && nkept < POST_NMS_N) {
            int b = __ffsll((long long)live) - 1;
            int i = (w << 6) + b;
            if (lane == 0) keptlist[nkept] = i;
            nkept++;
            if (lane == owner) {
                if (w < 32)      kb0 |= 1ULL << b;
                else if (w < 64) kb1 |= 1ULL << b;
                else             kb2 |= 1ULL << b;
            }
            const unsigned long long* row = g_mask + (size_t)i * MASK_W;
            remv0 |= row[lane];
            remv1 |= row[lane + 32];
            if (lane + 64 < MASK_W) remv2 |= row[lane + 64];
            unsigned long long supp2;
            if (w < 32)      supp2 = __shfl_sync(FULL, remv0, owner);
            else if (w < 64) supp2 = __shfl_sync(FULL, remv1, owner);
            else             supp2 = __shfl_sync(FULL, remv2, owner);
            live &= ~supp2;
            live &= ~(1ULL << b);
        }
    }

    for (int w = 0; w < MASK_W && nkept < POST_NMS_N; w++) {
        int owner = (w < 32) ? w : ((w < 64) ? w - 32 : w - 64);
        unsigned long long kw;
        if (w < 32)      kw = __shfl_sync(FULL, kb0, owner);
        else if (w < 64) kw = __shfl_sync(FULL, kb1, owner);
        else             kw = __shfl_sync(FULL, kb2, owner);
        unsigned long long live = ~kw;
        if (w == MASK_W - 1) live &= (1ULL << 48) - 1ULL;
        while (live && nkept < POST_NMS_N) {
            int b = __ffsll((long long)live) - 1;
            if (lane == 0) keptlist[nkept] = (w << 6) + b;
            nkept++;
            live &= live - 1;
        }
    }
    __syncwarp();
    for (int t = lane; t < POST_NMS_N; t += 32) g_sel[t] = keptlist[t];
}

__global__ void rois_kernel(float* __restrict__ out)
{
    int t = blockIdx.x * 64 + threadIdx.x;
    if (t >= POST_NMS_N) return;
    float4 b = g_top_boxes[g_sel[t]];
    out[t * 5 + 0] = 0.f;
    out[t * 5 + 1] = b.x;
    out[t * 5 + 2] = b.y;
    out[t * 5 + 3] = b.z;
    out[t * 5 + 4] = b.w;
}

extern "C" void kernel_launch(void* const* d_in, const int* in_sizes, int n_in,
                              void* d_out, int out_size)
{
    const float* feature_map = (const float*)d_in[0];
    const float* im_info     = (const float*)d_in[1];
    const float* conv_w      = (const float*)d_in[2];
    const float* conv_b      = (const float*)d_in[3];
    const float* cls_w       = (const float*)d_in[4];
    const float* cls_b       = (const float*)d_in[5];
    const float* bbox_w      = (const float*)d_in[6];
    const float* bbox_b      = (const float*)d_in[7];
    float* out = (float*)d_out;

    wino_w_kernel<<<(512 * 512 + 255) / 256, 256>>>(conv_w);
    wino_in_kernel<<<(512 * NTILE + 255) / 256, 256>>>(feature_map);
    wino_gemm_kernel<<<dim3(NTP / 128, 4, 16), 128>>>();
    wino_out_kernel<<<(512 * NTILE + 255) / 256, 256>>>(conv_b);

    zero_sel_kernel<<<(NCAND + 255) / 256, 256>>>();
    head_kernel<<<(NPIX + 63) / 64, 256>>>(cls_w, cls_b, bbox_w, bbox_b);
    decode_kernel<<<(NANCH + 255) / 256, 256>>>(im_info);

    scan1_kernel<<<1, 128>>>();
    hist2_kernel<<<(NANCH + 255) / 256, 256>>>();
    scan2_kernel<<<1, 128>>>();
    compact_kernel<<<(NANCH + 255) / 256, 256>>>();

    cand_local_kernel<<<NCAND / 4096, 1024>>>();
    cand_global_kernel<<<NCAND / 512, 256>>>(NCAND, NCAND / 2);
    cand_fused_kernel<<<NCAND / 4096, 1024>>>(NCAND);

    gather_kernel<<<(PRE_NMS_N + 255) / 256, 256>>>();
    dim3 mgrid(MASK_W, MASK_W);
    nms_mask_kernel<<<mgrid, 64>>>();
    nms_reduce_kernel<<<1, 32>>>();
    rois_kernel<<<(POST_NMS_N + 63) / 64, 64>>>(out);
}

// round 16
// speedup vs baseline: 1.1189x; 1.0024x over previous
#include <cuda_runtime.h>
#include <math.h>
#include <stdint.h>

#define W_ 152
#define H_ 100
#define NPIX 15200
#define NANCH 136800
#define NCAND 8192
#define NHIST 4096
#define PRE_NMS_N 6000
#define POST_NMS_N 300
#define MASK_W 94
#define NTILE 3800          // 50 x 76 winograd tiles
#define NTP 3840            // padded tile count (x128)
#define PLANE (512 * NTP)   // elements per winograd plane
#define NPAIR 1900          // 50 x 38 tile pairs

__device__ float g_U[16 * 512 * 512];
__device__ float g_V[16 * PLANE];
__device__ float g_M[16 * PLANE];
__device__ float g_x[512 * NPIX];
__device__ float g_head[54 * NPIX];
__device__ float4 g_boxes[NANCH];
__device__ unsigned long long g_keys[NANCH];
__device__ unsigned long long g_cand[NCAND];
__device__ int g_hist1[NHIST];
__device__ int g_hist2[NHIST];
__device__ int g_b1;
__device__ int g_above1;
__device__ unsigned g_T24;
__device__ int g_count;
__device__ float4 g_top_boxes[PRE_NMS_N];
__device__ unsigned long long g_mask[(size_t)PRE_NMS_N * MASK_W];
__device__ int g_sel[POST_NMS_N];

__constant__ float c_anchors[9][4] = {
    {-84.f,-40.f,99.f,55.f},{-176.f,-88.f,191.f,103.f},{-360.f,-184.f,375.f,199.f},
    {-56.f,-56.f,71.f,71.f},{-120.f,-120.f,135.f,135.f},{-248.f,-248.f,263.f,263.f},
    {-36.f,-80.f,51.f,95.f},{-80.f,-168.f,95.f,183.f},{-168.f,-344.f,183.f,359.f}
};

// ---- weight transform: U = G g G^T  (correlation form, exact halves)
__global__ __launch_bounds__(256) void wino_w_kernel(const float* __restrict__ wgt)
{
    int idx = blockIdx.x * 256 + threadIdx.x;
    if (idx >= 512 * 512) return;
    const float* g = wgt + (size_t)idx * 9;
    float t[4][3];
#pragma unroll
    for (int c = 0; c < 3; c++) {
        float g0 = g[c], g1 = g[3 + c], g2 = g[6 + c];
        t[0][c] = g0;
        t[1][c] = __fmul_rn(0.5f, __fadd_rn(__fadd_rn(g0, g1), g2));
        t[2][c] = __fmul_rn(0.5f, __fadd_rn(__fsub_rn(g0, g1), g2));
        t[3][c] = g2;
    }
#pragma unroll
    for (int i = 0; i < 4; i++) {
        float u0 = t[i][0];
        float u1 = __fmul_rn(0.5f, __fadd_rn(__fadd_rn(t[i][0], t[i][1]), t[i][2]));
        float u2 = __fmul_rn(0.5f, __fadd_rn(__fsub_rn(t[i][0], t[i][1]), t[i][2]));
        float u3 = t[i][2];
        g_U[(i * 4 + 0) * 262144 + idx] = u0;
        g_U[(i * 4 + 1) * 262144 + idx] = u1;
        g_U[(i * 4 + 2) * 262144 + idx] = u2;
        g_U[(i * 4 + 3) * 262144 + idx] = u3;
    }
}

// ---- input transform: V = B^T d B, 2 adjacent tiles per thread (identical math)
__global__ __launch_bounds__(256) void wino_in_kernel(const float* __restrict__ in)
{
    int idx = blockIdx.x * 256 + threadIdx.x;
    if (idx >= 512 * NPAIR) return;
    int ic = idx / NPAIR, pr = idx - ic * NPAIR;
    int trow = pr / 38, tc0 = (pr - trow * 38) * 2;
    int r0 = 2 * trow - 1, c0 = 2 * tc0 - 1;
    const float* src = in + (size_t)ic * NPIX;

    float d[4][6];
#pragma unroll
    for (int r = 0; r < 4; r++) {
        int rr = r0 + r;
        bool rv = (rr >= 0) && (rr < H_);
#pragma unroll
        for (int c = 0; c < 6; c++) {
            int cc = c0 + c;
            d[r][c] = (rv && cc >= 0 && cc < W_) ? src[rr * W_ + cc] : 0.f;
        }
    }

    size_t base = (size_t)ic * NTP + trow * 76 + tc0;
    float v0[16], v1[16];
#pragma unroll
    for (int tt = 0; tt < 2; tt++) {
        float* v = tt ? v1 : v0;
        int co = 2 * tt;
        float t[4][4];
#pragma unroll
        for (int c = 0; c < 4; c++) {
            t[0][c] = __fsub_rn(d[0][co + c], d[2][co + c]);
            t[1][c] = __fadd_rn(d[1][co + c], d[2][co + c]);
            t[2][c] = __fsub_rn(d[2][co + c], d[1][co + c]);
            t[3][c] = __fsub_rn(d[1][co + c], d[3][co + c]);
        }
#pragma unroll
        for (int i = 0; i < 4; i++) {
            v[i * 4 + 0] = __fsub_rn(t[i][0], t[i][2]);
            v[i * 4 + 1] = __fadd_rn(t[i][1], t[i][2]);
            v[i * 4 + 2] = __fsub_rn(t[i][2], t[i][1]);
            v[i * 4 + 3] = __fsub_rn(t[i][1], t[i][3]);
        }
    }
#pragma unroll
    for (int jj = 0; jj < 16; jj++)
        *reinterpret_cast<float2*>(&g_V[(size_t)jj * PLANE + base]) =
            make_float2(v0[jj], v1[jj]);
}

// ---- 16 batched GEMMs: M_j[512][3840] = U_j[512][512] x V_j[512][3840]
// R13 FFMA2 microkernel (inner loop byte-identical); vectorized B loader.
__global__ __launch_bounds__(128) void wino_gemm_kernel()
{
    __shared__ float As[2][8][132];
    __shared__ float Bs[2][8][132];
    const int tid = threadIdx.x;
    const int tx = tid & 7, ty = tid >> 3;
    const int bn = blockIdx.x * 128;
    const int bm = blockIdx.y * 128;
    const int j = blockIdx.z;
    const float* Up = g_U + (size_t)j * 262144 + (size_t)(bm + tid) * 512;
    const float* Vp = g_V + (size_t)j * PLANE;
    float* Mp = g_M + (size_t)j * PLANE;

    const int rB = tid >> 5;
    const int cB = (tid & 31) * 4;

    unsigned long long acc[8][8];
#pragma unroll
    for (int i = 0; i < 8; i++)
#pragma unroll
        for (int q = 0; q < 8; q++) acc[i][q] = 0ULL;

    float Areg[8];
    float4 Breg0, Breg1;
    auto loadTile = [&](int it) {
        int k0 = it * 8;
        float4 a0 = *reinterpret_cast<const float4*>(Up + k0);
        float4 a1 = *reinterpret_cast<const float4*>(Up + k0 + 4);
        Areg[0]=a0.x; Areg[1]=a0.y; Areg[2]=a0.z; Areg[3]=a0.w;
        Areg[4]=a1.x; Areg[5]=a1.y; Areg[6]=a1.z; Areg[7]=a1.w;
        Breg0 = *reinterpret_cast<const float4*>(
            Vp + (size_t)(k0 + rB) * NTP + bn + cB);
        Breg1 = *reinterpret_cast<const float4*>(
            Vp + (size_t)(k0 + rB + 4) * NTP + bn + cB);
    };
    auto storeTile = [&](int buf) {
#pragma unroll
        for (int kk = 0; kk < 8; kk++) As[buf][kk][tid] = Areg[kk];
        *reinterpret_cast<float4*>(&Bs[buf][rB][cB]) = Breg0;
        *reinterpret_cast<float4*>(&Bs[buf][rB + 4][cB]) = Breg1;
    };

    loadTile(0);
    storeTile(0);
    __syncthreads();

    int cur = 0;
    const int NIT = 64;
    for (int it = 0; it < NIT; it++) {
        bool more = (it + 1 < NIT);
        if (more) loadTile(it + 1);

#pragma unroll
        for (int kk = 0; kk < 8; kk++) {
            const float4* arow = reinterpret_cast<const float4*>(&As[cur][kk][0]);
            const ulonglong2* brow = reinterpret_cast<const ulonglong2*>(&Bs[cur][kk][0]);
            unsigned long long b2[8];
#pragma unroll
            for (int q = 0; q < 4; q++) {
                ulonglong2 t = brow[tx + q * 8];
                b2[2 * q] = t.x;
                b2[2 * q + 1] = t.y;
            }
            float4 a0 = arow[ty];
            float4 a1 = arow[ty + 16];
            float av[8];
            av[0]=a0.x; av[1]=a0.y; av[2]=a0.z; av[3]=a0.w;
            av[4]=a1.x; av[5]=a1.y; av[6]=a1.z; av[7]=a1.w;
            unsigned long long a2[8];
#pragma unroll
            for (int s = 0; s < 8; s++)
                asm("mov.b64 %0, {%1, %1};" : "=l"(a2[s]) : "f"(av[s]));
#pragma unroll
            for (int s = 0; s < 8; s++)
#pragma unroll
                for (int q = 0; q < 8; q++)
                    asm("fma.rn.f32x2 %0, %1, %2, %0;"
                        : "+l"(acc[s][q]) : "l"(a2[s]), "l"(b2[q]));
        }

        if (more) {
            storeTile(cur ^ 1);
            __syncthreads();
            cur ^= 1;
        }
    }

#pragma unroll
    for (int r = 0; r < 2; r++)
#pragma unroll
        for (int s = 0; s < 4; s++) {
            int m = bm + r * 64 + ty * 4 + s;
#pragma unroll
            for (int q = 0; q < 4; q++)
#pragma unroll
                for (int t = 0; t < 2; t++) {
                    int n = bn + q * 32 + tx * 4 + t * 2;
                    unsigned long long v = acc[r * 4 + s][q * 2 + t];
                    float lo, hi;
                    asm("mov.b64 {%0, %1}, %2;" : "=f"(lo), "=f"(hi) : "l"(v));
                    *reinterpret_cast<float2*>(&Mp[(size_t)m * NTP + n]) =
                        make_float2(lo, hi);
                }
        }
}

// ---- output transform: 2 adjacent tiles per thread (identical math)
__global__ __launch_bounds__(256) void wino_out_kernel(const float* __restrict__ bias)
{
    int idx = blockIdx.x * 256 + threadIdx.x;
    if (idx >= 512 * NPAIR) return;
    int oc = idx / NPAIR, pr = idx - oc * NPAIR;
    int trow = pr / 38, tc0 = (pr - trow * 38) * 2;
    size_t base = (size_t)oc * NTP + trow * 76 + tc0;

    float2 m2[16];
#pragma unroll
    for (int j = 0; j < 16; j++)
        m2[j] = *reinterpret_cast<const float2*>(&g_M[(size_t)j * PLANE + base]);

    float bv = bias[oc];
    float y[2][4];
#pragma unroll
    for (int tt = 0; tt < 2; tt++) {
        float m[16];
#pragma unroll
        for (int j = 0; j < 16; j++) m[j] = tt ? m2[j].y : m2[j].x;
        float t0[4], t1[4];
#pragma unroll
        for (int c = 0; c < 4; c++) {
            t0[c] = __fadd_rn(__fadd_rn(m[c], m[4 + c]), m[8 + c]);
            t1[c] = __fsub_rn(__fsub_rn(m[4 + c], m[8 + c]), m[12 + c]);
        }
        y[tt][0] = fmaxf(__fadd_rn(__fadd_rn(__fadd_rn(t0[0], t0[1]), t0[2]), bv), 0.f);
        y[tt][1] = fmaxf(__fadd_rn(__fsub_rn(__fsub_rn(t0[1], t0[2]), t0[3]), bv), 0.f);
        y[tt][2] = fmaxf(__fadd_rn(__fadd_rn(__fadd_rn(t1[0], t1[1]), t1[2]), bv), 0.f);
        y[tt][3] = fmaxf(__fadd_rn(__fsub_rn(__fsub_rn(t1[1], t1[2]), t1[3]), bv), 0.f);
    }
    float* dst = g_x + (size_t)oc * NPIX + (2 * trow) * W_ + 2 * tc0;
    *reinterpret_cast<float4*>(dst) =
        make_float4(y[0][0], y[0][1], y[1][0], y[1][1]);
    *reinterpret_cast<float4*>(dst + W_) =
        make_float4(y[0][2], y[0][3], y[1][2], y[1][3]);
}

// ---- heads: BN=64 (grid 238)
__global__ __launch_bounds__(256) void head_kernel(
    const float* __restrict__ cls_w, const float* __restrict__ cls_b,
    const float* __restrict__ bbox_w, const float* __restrict__ bbox_b)
{
    __shared__ float As[16][68];
    __shared__ float Bs[16][68];
    const int tid = threadIdx.x;
    const int bn = blockIdx.x * 64;
    const int tx = tid & 15, ty = tid >> 4;

    float acc[4][4];
#pragma unroll
    for (int i = 0; i < 4; i++)
#pragma unroll
        for (int j = 0; j < 4; j++) acc[i][j] = 0.f;

    for (int k0 = 0; k0 < 512; k0 += 16) {
        {
            int m = tid >> 2, kq = (tid & 3) << 2;
            float4 v = make_float4(0.f, 0.f, 0.f, 0.f);
            if (m < 18) v = *reinterpret_cast<const float4*>(cls_w + (size_t)m * 512 + k0 + kq);
            else if (m < 54) v = *reinterpret_cast<const float4*>(bbox_w + (size_t)(m - 18) * 512 + k0 + kq);
            As[kq + 0][m] = v.x; As[kq + 1][m] = v.y; As[kq + 2][m] = v.z; As[kq + 3][m] = v.w;
        }
#pragma unroll
        for (int r = 0; r < 4; r++) {
            int e = r * 256 + tid, kk = e >> 6, nn = e & 63, p = bn + nn;
            Bs[kk][nn] = (p < NPIX) ? g_x[(size_t)(k0 + kk) * NPIX + p] : 0.f;
        }
        __syncthreads();
#pragma unroll
        for (int kk = 0; kk < 16; kk++) {
            float a[4], b[4];
            float4 a0 = *reinterpret_cast<float4*>(&As[kk][ty * 4]);
            float4 b0 = *reinterpret_cast<float4*>(&Bs[kk][tx * 4]);
            a[0]=a0.x; a[1]=a0.y; a[2]=a0.z; a[3]=a0.w;
            b[0]=b0.x; b[1]=b0.y; b[2]=b0.z; b[3]=b0.w;
#pragma unroll
            for (int i = 0; i < 4; i++)
#pragma unroll
                for (int j = 0; j < 4; j++)
                    acc[i][j] = __fmaf_rn(a[i], b[j], acc[i][j]);
        }
        __syncthreads();
    }
#pragma unroll
    for (int i = 0; i < 4; i++) {
        int m = ty * 4 + i;
        if (m >= 54) continue;
        float bv = (m < 18) ? cls_b[m] : bbox_b[m - 18];
#pragma unroll
        for (int j = 0; j < 4; j++) {
            int n = bn + tx * 4 + j;
            if (n < NPIX) g_head[(size_t)m * NPIX + n] = __fadd_rn(acc[i][j], bv);
        }
    }
}

__global__ void zero_sel_kernel()
{
    int idx = blockIdx.x * 256 + threadIdx.x;
    if (idx < NCAND) g_cand[idx] = 0ULL;
    if (idx < NHIST) { g_hist1[idx] = 0; g_hist2[idx] = 0; }
    if (idx == 0) g_count = 0;
}

// ---- decode: p-major thread mapping (coalesced head reads); values identical
__global__ void decode_kernel(const float* __restrict__ iminfo)
{
    int idx = blockIdx.x * 256 + threadIdx.x;
    if (idx >= NANCH) return;
    int a = idx / NPIX, p = idx - a * NPIX;
    int h = p / W_, w = p - h * W_;

    float s0 = g_head[(size_t)a * NPIX + p];
    float s1 = g_head[(size_t)(9 + a) * NPIX + p];
    float mx = fmaxf(s0, s1);
    float e0 = (float)exp((double)__fsub_rn(s0, mx));
    float e1 = (float)exp((double)__fsub_rn(s1, mx));
    float fg = __fdiv_rn(e1, __fadd_rn(e0, e1));

    float d0 = g_head[(size_t)(18 + a * 4 + 0) * NPIX + p];
    float d1 = g_head[(size_t)(18 + a * 4 + 1) * NPIX + p];
    float d2 = g_head[(size_t)(18 + a * 4 + 2) * NPIX + p];
    float d3 = g_head[(size_t)(18 + a * 4 + 3) * NPIX + p];

    float sx = (float)(w * 16), sy = (float)(h * 16);
    float x1a = c_anchors[a][0] + sx, y1a = c_anchors[a][1] + sy;
    float x2a = c_anchors[a][2] + sx, y2a = c_anchors[a][3] + sy;
    float aw = __fadd_rn(__fsub_rn(x2a, x1a), 1.0f);
    float ah = __fadd_rn(__fsub_rn(y2a, y1a), 1.0f);
    float ax = __fadd_rn(x1a, __fmul_rn(0.5f, aw));
    float ay = __fadd_rn(y1a, __fmul_rn(0.5f, ah));

    float px = __fadd_rn(__fmul_rn(d0, aw), ax);
    float py = __fadd_rn(__fmul_rn(d1, ah), ay);
    float pwv = __fmul_rn((float)exp((double)d2), aw);
    float phv = __fmul_rn((float)exp((double)d3), ah);

    float x1 = __fsub_rn(px, __fmul_rn(0.5f, pwv));
    float y1 = __fsub_rn(py, __fmul_rn(0.5f, phv));
    float x2 = __fadd_rn(px, __fmul_rn(0.5f, pwv));
    float y2 = __fadd_rn(py, __fmul_rn(0.5f, phv));

    float hiX = __fsub_rn(iminfo[1], 1.0f);
    float hiY = __fsub_rn(iminfo[0], 1.0f);
    x1 = fminf(fmaxf(x1, 0.f), hiX);
    y1 = fminf(fmaxf(y1, 0.f), hiY);
    x2 = fminf(fmaxf(x2, 0.f), hiX);
    y2 = fminf(fmaxf(y2, 0.f), hiY);

    float ws = __fadd_rn(__fsub_rn(x2, x1), 1.0f);
    float hs = __fadd_rn(__fsub_rn(y2, y1), 1.0f);
    float msz = __fmul_rn(16.0f, iminfo[2]);
    bool valid = (ws >= msz) && (hs >= msz);
    float score = valid ? fg : -1000000000.0f;

    int orig = p * 9 + a;
    unsigned u = __float_as_uint(score);
    u = (u & 0x80000000u) ? ~u : (u | 0x80000000u);
    g_keys[orig] = ((unsigned long long)u << 32) | (unsigned)(~(unsigned)orig);
    g_boxes[orig] = make_float4(x1, y1, x2, y2);
    atomicAdd(&g_hist1[u >> 20], 1);
}

__global__ __launch_bounds__(128) void scan1_kernel()
{
    __shared__ int part[128];
    int t = threadIdx.x, s = 0;
#pragma unroll
    for (int q = 0; q < 32; q++) s += g_hist1[t * 32 + q];
    part[t] = s;
    __syncthreads();
    if (t == 0) {
        int cum = 0, seg = 0;
        for (int pp = 127; pp >= 0; pp--) {
            if (cum + part[pp] >= PRE_NMS_N) { seg = pp; break; }
            cum += part[pp];
            if (pp == 0) seg = 0;
        }
        int b = seg * 32 + 31;
        for (; b >= seg * 32; b--) {
            int c = g_hist1[b];
            if (cum + c >= PRE_NMS_N) break;
            cum += c;
        }
        if (b < seg * 32) b = seg * 32;
        g_b1 = b; g_above1 = cum;
    }
}

__global__ void hist2_kernel()
{
    int idx = blockIdx.x * 256 + threadIdx.x;
    if (idx >= NANCH) return;
    unsigned u = (unsigned)(g_keys[idx] >> 32);
    if ((int)(u >> 20) == g_b1) atomicAdd(&g_hist2[(u >> 8) & 0xFFF], 1);
}

__global__ __launch_bounds__(128) void scan2_kernel()
{
    __shared__ int part[128];
    int t = threadIdx.x, s = 0;
#pragma unroll
    for (int q = 0; q < 32; q++) s += g_hist2[t * 32 + q];
    part[t] = s;
    __syncthreads();
    if (t == 0) {
        int cum = g_above1, seg = 0;
        for (int pp = 127; pp >= 0; pp--) {
            if (cum + part[pp] >= PRE_NMS_N) { seg = pp; break; }
            cum += part[pp];
            if (pp == 0) seg = 0;
        }
        int b = seg * 32 + 31;
        for (; b >= seg * 32; b--) {
            int c = g_hist2[b];
            if (cum + c >= PRE_NMS_N) break;
            cum += c;
        }
        if (b < seg * 32) b = seg * 32;
        g_T24 = ((unsigned)g_b1 << 12) | (unsigned)b;
    }
}

__global__ void compact_kernel()
{
    int idx = blockIdx.x * 256 + threadIdx.x;
    if (idx >= NANCH) return;
    unsigned long long key = g_keys[idx];
    unsigned u = (unsigned)(key >> 32);
    if ((u >> 8) >= g_T24) {
        int pos = atomicAdd(&g_count, 1);
        if (pos < NCAND) g_cand[pos] = key;
    }
}

__device__ __forceinline__ bool bt_sw(unsigned long long a, unsigned long long b, bool up)
{
    return up ? (a > b) : (a < b);
}

__global__ __launch_bounds__(1024) void cand_local_kernel()
{
    __shared__ unsigned long long s[4096];
    int base = blockIdx.x * 4096;
    for (int e = threadIdx.x; e < 4096; e += 1024) s[e] = g_cand[base + e];
    __syncthreads();
    for (int k = 2; k <= 4096; k <<= 1)
        for (int j = k >> 1; j > 0; j >>= 1) {
            for (int t = threadIdx.x; t < 2048; t += 1024) {
                int i1 = ((t & ~(j - 1)) << 1) | (t & (j - 1));
                int i2 = i1 + j;
                bool up = (((base + i1) & k) != 0);
                unsigned long long a = s[i1], b = s[i2];
                if (bt_sw(a, b, up)) { s[i1] = b; s[i2] = a; }
            }
            __syncthreads();
        }
    for (int e = threadIdx.x; e < 4096; e += 1024) g_cand[base + e] = s[e];
}

__global__ __launch_bounds__(256) void cand_global_kernel(int k, int j)
{
    int t = blockIdx.x * 256 + threadIdx.x;
    int i1 = ((t & ~(j - 1)) << 1) | (t & (j - 1));
    int i2 = i1 + j;
    bool up = ((i1 & k) != 0);
    unsigned long long a = g_cand[i1], b = g_cand[i2];
    if (bt_sw(a, b, up)) { g_cand[i1] = b; g_cand[i2] = a; }
}

__global__ __launch_bounds__(1024) void cand_fused_kernel(int k)
{
    __shared__ unsigned long long s[4096];
    int base = blockIdx.x * 4096;
    for (int e = threadIdx.x; e < 4096; e += 1024) s[e] = g_cand[base + e];
    __syncthreads();
    for (int j = 2048; j > 0; j >>= 1) {
        for (int t = threadIdx.x; t < 2048; t += 1024) {
            int i1 = ((t & ~(j - 1)) << 1) | (t & (j - 1));
            int i2 = i1 + j;
            bool up = (((base + i1) & k) != 0);
            unsigned long long a = s[i1], b = s[i2];
            if (bt_sw(a, b, up)) { s[i1] = b; s[i2] = a; }
        }
        __syncthreads();
    }
    for (int e = threadIdx.x; e < 4096; e += 1024) g_cand[base + e] = s[e];
}

__global__ void gather_kernel()
{
    int i = blockIdx.x * 256 + threadIdx.x;
    if (i >= PRE_NMS_N) return;
    unsigned idx = ~((unsigned)(g_cand[i] & 0xFFFFFFFFULL));
    g_top_boxes[i] = g_boxes[idx];
}

__global__ __launch_bounds__(64) void nms_mask_kernel()
{
    int rb = blockIdx.y, cb = blockIdx.x;
    if (cb < rb) return;
    __shared__ float4 cbox[64];
    int tid = threadIdx.x;
    int col0 = cb * 64;
    int ccount = min(PRE_NMS_N - col0, 64);
    if (tid < ccount) cbox[tid] = g_top_boxes[col0 + tid];
    __syncthreads();
    int i = rb * 64 + tid;
    if (i >= PRE_NMS_N) return;
    float4 bi = g_top_boxes[i];
    float ai = __fmul_rn(__fadd_rn(__fsub_rn(bi.z, bi.x), 1.0f),
                         __fadd_rn(__fsub_rn(bi.w, bi.y), 1.0f));
    unsigned long long bits = 0ULL;
    for (int c = 0; c < ccount; c++) {
        int j = col0 + c;
        if (j <= i) continue;
        float4 bj = cbox[c];
        float xx1 = fmaxf(bi.x, bj.x), yy1 = fmaxf(bi.y, bj.y);
        float xx2 = fminf(bi.z, bj.z), yy2 = fminf(bi.w, bj.w);
        float iw = fmaxf(0.f, __fadd_rn(__fsub_rn(xx2, xx1), 1.0f));
        float ih = fmaxf(0.f, __fadd_rn(__fsub_rn(yy2, yy1), 1.0f));
        float inter = __fmul_rn(iw, ih);
        float aj = __fmul_rn(__fadd_rn(__fsub_rn(bj.z, bj.x), 1.0f),
                             __fadd_rn(__fsub_rn(bj.w, bj.y), 1.0f));
        float iou = __fdiv_rn(inter, __fsub_rn(__fadd_rn(ai, aj), inter));
        if (iou > 0.7f) bits |= (1ULL << c);
    }
    g_mask[(size_t)i * MASK_W + cb] = bits;
}

__global__ __launch_bounds__(32) void nms_reduce_kernel()
{
    __shared__ int keptlist[POST_NMS_N];
    const unsigned FULL = 0xffffffffu;
    int lane = threadIdx.x;
    unsigned long long remv0 = 0, remv1 = 0, remv2 = 0;
    unsigned long long kb0 = 0, kb1 = 0, kb2 = 0;
    int nkept = 0;

    for (int w = 0; w < MASK_W && nkept < POST_NMS_N; w++) {
        int owner = (w < 32) ? w : ((w < 64) ? w - 32 : w - 64);
        unsigned long long supp;
        if (w < 32)      supp = __shfl_sync(FULL, remv0, owner);
        else if (w < 64) supp = __shfl_sync(FULL, remv1, owner);
        else             supp = __shfl_sync(FULL, remv2, owner);
        unsigned long long live = ~supp;
        if (w == MASK_W - 1) live &= (1ULL << 48) - 1ULL;

        while (live && nkept < POST_NMS_N) {
            int b = __ffsll((long long)live) - 1;
            int i = (w << 6) + b;
            if (lane == 0) keptlist[nkept] = i;
            nkept++;
            if (lane == owner) {
                if (w < 32)      kb0 |= 1ULL << b;
                else if (w < 64) kb1 |= 1ULL << b;
                else             kb2 |= 1ULL << b;
            }
            const unsigned long long* row = g_mask + (size_t)i * MASK_W;
            remv0 |= row[lane];
            remv1 |= row[lane + 32];
            if (lane + 64 < MASK_W) remv2 |= row[lane + 64];
            unsigned long long supp2;
            if (w < 32)      supp2 = __shfl_sync(FULL, remv0, owner);
            else if (w < 64) supp2 = __shfl_sync(FULL, remv1, owner);
            else             supp2 = __shfl_sync(FULL, remv2, owner);
            live &= ~supp2;
            live &= ~(1ULL << b);
        }
    }

    for (int w = 0; w < MASK_W && nkept < POST_NMS_N; w++) {
        int owner = (w < 32) ? w : ((w < 64) ? w - 32 : w - 64);
        unsigned long long kw;
        if (w < 32)      kw = __shfl_sync(FULL, kb0, owner);
        else if (w < 64) kw = __shfl_sync(FULL, kb1, owner);
        else             kw = __shfl_sync(FULL, kb2, owner);
        unsigned long long live = ~kw;
        if (w == MASK_W - 1) live &= (1ULL << 48) - 1ULL;
        while (live && nkept < POST_NMS_N) {
            int b = __ffsll((long long)live) - 1;
            if (lane == 0) keptlist[nkept] = (w << 6) + b;
            nkept++;
            live &= live - 1;
        }
    }
    __syncwarp();
    for (int t = lane; t < POST_NMS_N; t += 32) g_sel[t] = keptlist[t];
}

__global__ void rois_kernel(float* __restrict__ out)
{
    int t = blockIdx.x * 64 + threadIdx.x;
    if (t >= POST_NMS_N) return;
    float4 b = g_top_boxes[g_sel[t]];
    out[t * 5 + 0] = 0.f;
    out[t * 5 + 1] = b.x;
    out[t * 5 + 2] = b.y;
    out[t * 5 + 3] = b.z;
    out[t * 5 + 4] = b.w;
}

extern "C" void kernel_launch(void* const* d_in, const int* in_sizes, int n_in,
                              void* d_out, int out_size)
{
    const float* feature_map = (const float*)d_in[0];
    const float* im_info     = (const float*)d_in[1];
    const float* conv_w      = (const float*)d_in[2];
    const float* conv_b      = (const float*)d_in[3];
    const float* cls_w       = (const float*)d_in[4];
    const float* cls_b       = (const float*)d_in[5];
    const float* bbox_w      = (const float*)d_in[6];
    const float* bbox_b      = (const float*)d_in[7];
    float* out = (float*)d_out;

    wino_w_kernel<<<(512 * 512 + 255) / 256, 256>>>(conv_w);
    wino_in_kernel<<<(512 * NPAIR + 255) / 256, 256>>>(feature_map);
    wino_gemm_kernel<<<dim3(NTP / 128, 4, 16), 128>>>();
    wino_out_kernel<<<(512 * NPAIR + 255) / 256, 256>>>(conv_b);

    zero_sel_kernel<<<(NCAND + 255) / 256, 256>>>();
    head_kernel<<<(NPIX + 63) / 64, 256>>>(cls_w, cls_b, bbox_w, bbox_b);
    decode_kernel<<<(NANCH + 255) / 256, 256>>>(im_info);

    scan1_kernel<<<1, 128>>>();
    hist2_kernel<<<(NANCH + 255) / 256, 256>>>();
    scan2_kernel<<<1, 128>>>();
    compact_kernel<<<(NANCH + 255) / 256, 256>>>();

    cand_local_kernel<<<NCAND / 4096, 1024>>>();
    cand_global_kernel<<<NCAND / 512, 256>>>(NCAND, NCAND / 2);
    cand_fused_kernel<<<NCAND / 4096, 1024>>>(NCAND);

    gather_kernel<<<(PRE_NMS_N + 255) / 256, 256>>>();
    dim3 mgrid(MASK_W, MASK_W);
    nms_mask_kernel<<<mgrid, 64>>>();
    nms_reduce_kernel<<<1, 32>>>();
    rois_kernel<<<(POST_NMS_N + 63) / 64, 64>>>(out);
}